// round 12
// baseline (speedup 1.0000x reference)
#include <cuda_runtime.h>
#include <cuda_bf16.h>
#include <math.h>

#define NUM_C 1000
#define DIMS  256
#define NMAX  262144
#define CAP   512      // per-class slot capacity (mean 262, sd ~16)
#define TI_N  16       // 64-row A tiles
#define GRID_GRAM 272  // tiles (ti, tj) with tj >= 2*ti, tj < 32
#define SROW  132      // smem row stride in 32-bit words (128 data + 4 pad)

// ---- device scratch (zero-initialized at load; kernels restore zeros for graph replay) ----
__device__ int      g_cursor[NUM_C];     // per-class element count (reset by gather_k)
__device__ int      g_idx[NUM_C * CAP];
__device__ unsigned g_hi[NUM_C * 128];   // bf16x2 hi plane of normalized means
__device__ unsigned g_lo[NUM_C * 128];   // bf16x2 lo plane
__device__ int      g_maxkey;            // float-as-int key of (max_dot + 4.0f); reset by grammax_k
__device__ int      g_done;              // gram completion ticket; reset by grammax_k

__device__ __forceinline__ void mma_bf16(float& c0, float& c1, float& c2, float& c3,
                                         unsigned a0, unsigned a1, unsigned a2, unsigned a3,
                                         unsigned b0, unsigned b1) {
    asm("mma.sync.aligned.m16n8k16.row.col.f32.bf16.bf16.f32 "
        "{%0,%1,%2,%3}, {%4,%5,%6,%7}, {%8,%9}, {%0,%1,%2,%3};"
        : "+f"(c0), "+f"(c1), "+f"(c2), "+f"(c3)
        : "r"(a0), "r"(a1), "r"(a2), "r"(a3), "r"(b0), "r"(b1));
}

__device__ __forceinline__ void ldsm_x4(unsigned& r0, unsigned& r1, unsigned& r2, unsigned& r3,
                                        unsigned addr) {
    asm volatile("ldmatrix.sync.aligned.m8n8.x4.shared.b16 {%0,%1,%2,%3}, [%4];"
        : "=r"(r0), "=r"(r1), "=r"(r2), "=r"(r3) : "r"(addr));
}

__device__ __forceinline__ unsigned smem_u32(const void* p) {
    unsigned a;
    asm("{ .reg .u64 t; cvta.to.shared.u64 t, %1; cvt.u32.u64 %0, t; }" : "=r"(a) : "l"(p));
    return a;
}

// ---------------------------------------------------------------------------
__global__ void scatter_k(const int* __restrict__ labels, int n) {
    int i = blockIdx.x * blockDim.x + threadIdx.x;
    if (i < n) {
        int lab = labels[i];
        int pos = lab * CAP + atomicAdd(&g_cursor[lab], 1);
        g_idx[pos] = i;
    }
}

// One CTA per class (R4-proven body). Epilogue emits split-bf16 hi/lo planes.
// Resets g_cursor[c] = 0 at the end for the next graph replay.
__global__ void __launch_bounds__(256) gather_k(const float* __restrict__ f) {
    int c = blockIdx.x;
    int t = threadIdx.x;
    int beg = c * CAP;
    int cnt = g_cursor[c];
    int quad = t >> 6;
    int col  = t & 63;

    __shared__ int    sidx[256];
    __shared__ float4 sacc[256];
    __shared__ float  wsum[8];
    __shared__ float  sinv;

    const float4* f4 = (const float4*)f;
    float4 acc = make_float4(0.f, 0.f, 0.f, 0.f);

    for (int base = 0; base < cnt; base += 256) {
        int m = cnt - base; if (m > 256) m = 256;
        __syncthreads();
        if (t < m) sidx[t] = g_idx[beg + base + t];
        __syncthreads();
        int r = quad;
        for (; r + 12 < m; r += 16) {
            float4 v0 = f4[(long)sidx[r     ] * 64 + col];
            float4 v1 = f4[(long)sidx[r +  4] * 64 + col];
            float4 v2 = f4[(long)sidx[r +  8] * 64 + col];
            float4 v3 = f4[(long)sidx[r + 12] * 64 + col];
            acc.x += v0.x + v1.x + v2.x + v3.x;
            acc.y += v0.y + v1.y + v2.y + v3.y;
            acc.z += v0.z + v1.z + v2.z + v3.z;
            acc.w += v0.w + v1.w + v2.w + v3.w;
        }
        for (; r < m; r += 4) {
            float4 v = f4[(long)sidx[r] * 64 + col];
            acc.x += v.x; acc.y += v.y; acc.z += v.z; acc.w += v.w;
        }
    }

    sacc[t] = acc;
    __syncthreads();

    float4 mean = make_float4(0.f, 0.f, 0.f, 0.f);
    float ss = 0.f;
    if (t < 64) {
        float4 a = sacc[t], b = sacc[t + 64], c2 = sacc[t + 128], d = sacc[t + 192];
        float inv = 1.0f / (float)((cnt > 0) ? cnt : 1);
        mean.x = (a.x + b.x + c2.x + d.x) * inv;
        mean.y = (a.y + b.y + c2.y + d.y) * inv;
        mean.z = (a.z + b.z + c2.z + d.z) * inv;
        mean.w = (a.w + b.w + c2.w + d.w) * inv;
        ss = mean.x * mean.x + mean.y * mean.y + mean.z * mean.z + mean.w * mean.w;
    }
    #pragma unroll
    for (int o = 16; o > 0; o >>= 1) ss += __shfl_xor_sync(0xffffffffu, ss, o);
    if ((t & 31) == 0) wsum[t >> 5] = ss;
    __syncthreads();
    if (t == 0) {
        float tot = 0.f;
        #pragma unroll
        for (int w = 0; w < 8; w++) tot += wsum[w];
        sinv = (tot > 0.f) ? rsqrtf(tot) : 0.f;
    }
    __syncthreads();
    if (t < 64) {
        float s = sinv;
        float v[4] = {mean.x * s, mean.y * s, mean.z * s, mean.w * s};
        unsigned h[4], l[4];
        #pragma unroll
        for (int i = 0; i < 4; i++) {
            __nv_bfloat16 hb = __float2bfloat16(v[i]);
            float res = v[i] - __bfloat162float(hb);
            __nv_bfloat16 lb = __float2bfloat16(res);
            h[i] = __bfloat16_as_ushort(hb);
            l[i] = __bfloat16_as_ushort(lb);
        }
        g_hi[c * 128 + 2 * t    ] = h[0] | (h[1] << 16);
        g_hi[c * 128 + 2 * t + 1] = h[2] | (h[3] << 16);
        g_lo[c * 128 + 2 * t    ] = l[0] | (l[1] << 16);
        g_lo[c * 128 + 2 * t + 1] = l[2] | (l[3] << 16);
    }
    if (t == 0) g_cursor[c] = 0;    // restore for next graph replay
}

// Tensor-core gram-max, 64x32 tiles for 2 CTAs/SM.
// 8 warps (4 row x 2 col); warp = 16 rows x 16 cols (2 n8 tiles).
// Per k16 step: 4 ldmatrix.x4 + 6 mma. Split-bf16 3-term product.
__global__ void __launch_bounds__(256, 2) grammax_k(float* out, int n_out) {
    extern __shared__ unsigned smw[];
    unsigned* sAh = smw;                    // 64 x SROW
    unsigned* sAl = smw + 64 * SROW;        // 64 x SROW
    unsigned* sBh = smw + 128 * SROW;       // 32 x SROW
    unsigned* sBl = smw + 160 * SROW;       // 32 x SROW

    int b = blockIdx.x;
    int ti = 0, len = 32;
    while (b >= len) { b -= len; ti++; len -= 2; }
    int tj = 2 * ti + b;

    int t = threadIdx.x;

    // stage A planes: 64 rows x 128 words each
    #pragma unroll
    for (int p = 0; p < 32; p++) {
        int idx = p * 256 + t;
        int r = idx >> 7;
        int cw = idx & 127;
        int rA = ti * 64 + r;
        unsigned ah = (rA < NUM_C) ? g_hi[rA * 128 + cw] : 0u;
        unsigned al = (rA < NUM_C) ? g_lo[rA * 128 + cw] : 0u;
        sAh[r * SROW + cw] = ah;
        sAl[r * SROW + cw] = al;
    }
    // stage B planes: 32 rows x 128 words each
    #pragma unroll
    for (int p = 0; p < 16; p++) {
        int idx = p * 256 + t;
        int r = idx >> 7;
        int cw = idx & 127;
        int rB = tj * 32 + r;
        unsigned bh = (rB < NUM_C) ? g_hi[rB * 128 + cw] : 0u;
        unsigned bl = (rB < NUM_C) ? g_lo[rB * 128 + cw] : 0u;
        sBh[r * SROW + cw] = bh;
        sBl[r * SROW + cw] = bl;
    }
    __syncthreads();

    int w    = t >> 5;
    int lane = t & 31;
    int wrow = (w & 3) * 16;
    int wcol = (w >> 2) * 16;
    int lr   = lane >> 2;     // epilogue row-in-frag
    int lk   = lane & 3;

    int lr8 = lane & 7, grp = lane >> 3;
    int aRow = wrow + lr8 + ((grp & 1) << 3);
    int aK   = (grp >> 1) << 2;
    int bRow = wcol + lr8 + ((grp >> 1) << 3);
    int bK   = (grp & 1) << 2;

    unsigned uAhi = smem_u32(sAh) + 4u * (aRow * SROW + aK);
    unsigned uAlo = uAhi + 4u * 64 * SROW;
    unsigned uBhi = smem_u32(sBh) + 4u * (bRow * SROW + bK);
    unsigned uBlo = uBhi + 4u * 32 * SROW;

    float acc[2][4];
    #pragma unroll
    for (int tn = 0; tn < 2; tn++)
        #pragma unroll
        for (int i = 0; i < 4; i++) acc[tn][i] = 0.f;

    #pragma unroll
    for (int kk = 0; kk < 16; kk++) {
        unsigned ah0,ah1,ah2,ah3, al0,al1,al2,al3;
        ldsm_x4(ah0, ah1, ah2, ah3, uAhi);
        ldsm_x4(al0, al1, al2, al3, uAlo);
        unsigned b00h,b01h,b10h,b11h, b00l,b01l,b10l,b11l;
        ldsm_x4(b00h, b01h, b10h, b11h, uBhi);   // tn0 {b0,b1}, tn1 {b0,b1}
        ldsm_x4(b00l, b01l, b10l, b11l, uBlo);

        mma_bf16(acc[0][0],acc[0][1],acc[0][2],acc[0][3], ah0,ah1,ah2,ah3, b00h,b01h);
        mma_bf16(acc[0][0],acc[0][1],acc[0][2],acc[0][3], ah0,ah1,ah2,ah3, b00l,b01l);
        mma_bf16(acc[0][0],acc[0][1],acc[0][2],acc[0][3], al0,al1,al2,al3, b00h,b01h);

        mma_bf16(acc[1][0],acc[1][1],acc[1][2],acc[1][3], ah0,ah1,ah2,ah3, b10h,b11h);
        mma_bf16(acc[1][0],acc[1][1],acc[1][2],acc[1][3], ah0,ah1,ah2,ah3, b10l,b11l);
        mma_bf16(acc[1][0],acc[1][1],acc[1][2],acc[1][3], al0,al1,al2,al3, b10h,b11h);

        uAhi += 32; uAlo += 32; uBhi += 32; uBlo += 32;
    }

    // mask to strict upper triangle, reduce max
    float lm = -4.0f;
    int gi0 = ti * 64 + wrow + lr;
    #pragma unroll
    for (int tn = 0; tn < 2; tn++) {
        int gj0 = tj * 32 + wcol + tn * 8 + 2 * lk;
        if (gi0     < gj0     && gj0     < NUM_C) lm = fmaxf(lm, acc[tn][0]);
        if (gi0     < gj0 + 1 && gj0 + 1 < NUM_C) lm = fmaxf(lm, acc[tn][1]);
        if (gi0 + 8 < gj0     && gj0     < NUM_C) lm = fmaxf(lm, acc[tn][2]);
        if (gi0 + 8 < gj0 + 1 && gj0 + 1 < NUM_C) lm = fmaxf(lm, acc[tn][3]);
    }
    #pragma unroll
    for (int o = 16; o > 0; o >>= 1) lm = fmaxf(lm, __shfl_xor_sync(0xffffffffu, lm, o));
    __shared__ float wm[8];
    if (lane == 0) wm[w] = lm;
    __syncthreads();
    if (t == 0) {
        float m = wm[0];
        #pragma unroll
        for (int q = 1; q < 8; q++) m = fmaxf(m, wm[q]);
        atomicMax(&g_maxkey, __float_as_int(m + 4.0f));
        __threadfence();
        int ticket = atomicAdd(&g_done, 1);
        if (ticket == gridDim.x - 1) {
            float maxd = __int_as_float(*(volatile int*)&g_maxkey) - 4.0f;
            maxd = fminf(fmaxf(maxd, -1.f), 1.f);
            float mind = 1.0f - maxd;
            float loss = logf(1.0f / (mind + 1e-6f) + 1.0f);
            for (int i = 0; i < n_out; i++) out[i] = loss;
            g_maxkey = 0;    // restore for next graph replay
            g_done = 0;
        }
    }
}

// ---------------------------------------------------------------------------
extern "C" void kernel_launch(void* const* d_in, const int* in_sizes, int n_in,
                              void* d_out, int out_size) {
    const float* features = (const float*)d_in[0];
    const int*   labels   = (const int*)d_in[1];
    int n = in_sizes[1];

    const int smem_gram = 192 * SROW * (int)sizeof(unsigned); // 101376 B
    cudaFuncSetAttribute(grammax_k, cudaFuncAttributeMaxDynamicSharedMemorySize, smem_gram);

    scatter_k<<<(n + 255) / 256, 256>>>(labels, n);
    gather_k<<<NUM_C, 256>>>(features);
    grammax_k<<<GRID_GRAM, 256, smem_gram>>>((float*)d_out, out_size);
}

// round 13
// speedup vs baseline: 1.2661x; 1.2661x over previous
#include <cuda_runtime.h>
#include <cuda_bf16.h>
#include <math.h>

#define NUM_C 1000
#define DIMS  256
#define NMAX  262144
#define SUBS    32     // sub-slots per class (atomic de-contention)
#define SUBCAP  32     // capacity per sub-slot (mean 8.2, >7 sd)
#define CAP   (SUBS * SUBCAP)   // 1024 per class
#define TILES 16       // ceil(1000/64)
#define SROW  132      // smem row stride in 32-bit words (128 data + 4 pad)

// ---- device scratch (zero-initialized at load; kernels restore zeros for graph replay) ----
__device__ int      g_cursor[NUM_C * SUBS];  // per (class,sub) counts; reset by gather_k
__device__ int      g_idx[NUM_C * CAP];
__device__ unsigned g_hi[NUM_C * 128];   // bf16x2 hi plane of normalized means
__device__ unsigned g_lo[NUM_C * 128];   // bf16x2 lo plane
__device__ int      g_maxkey;            // float-as-int key of (max_dot + 4.0f); reset by grammax_k
__device__ int      g_done;              // gram completion ticket; reset by grammax_k

__device__ __forceinline__ void mma_bf16(float& c0, float& c1, float& c2, float& c3,
                                         unsigned a0, unsigned a1, unsigned a2, unsigned a3,
                                         unsigned b0, unsigned b1) {
    asm("mma.sync.aligned.m16n8k16.row.col.f32.bf16.bf16.f32 "
        "{%0,%1,%2,%3}, {%4,%5,%6,%7}, {%8,%9}, {%0,%1,%2,%3};"
        : "+f"(c0), "+f"(c1), "+f"(c2), "+f"(c3)
        : "r"(a0), "r"(a1), "r"(a2), "r"(a3), "r"(b0), "r"(b1));
}

__device__ __forceinline__ void ldsm_x4(unsigned& r0, unsigned& r1, unsigned& r2, unsigned& r3,
                                        unsigned addr) {
    asm volatile("ldmatrix.sync.aligned.m8n8.x4.shared.b16 {%0,%1,%2,%3}, [%4];"
        : "=r"(r0), "=r"(r1), "=r"(r2), "=r"(r3) : "r"(addr));
}

__device__ __forceinline__ unsigned smem_u32(const void* p) {
    unsigned a;
    asm("{ .reg .u64 t; cvta.to.shared.u64 t, %1; cvt.u32.u64 %0, t; }" : "=r"(a) : "l"(p));
    return a;
}

// ---------------------------------------------------------------------------
// 32 sub-cursors per class: lanes in a warp hit 32 distinct sub-slots, expected
// per-address contention ~8 (vs 262 with one counter per class).
__global__ void scatter_k(const int* __restrict__ labels, int n) {
    int i = blockIdx.x * blockDim.x + threadIdx.x;
    if (i < n) {
        int lab = labels[i];
        int sub = i & (SUBS - 1);
        int pos = atomicAdd(&g_cursor[lab * SUBS + sub], 1);
        g_idx[lab * CAP + sub * SUBCAP + pos] = i;
    }
}

// One CTA per class. Prologue: warp-scan 32 sub-counts, compact indices into smem
// (and reset cursors for graph replay). Main loop: R4-proven column-gather.
// Epilogue: split-bf16 hi/lo planes.
__global__ void __launch_bounds__(256) gather_k(const float* __restrict__ f) {
    int c = blockIdx.x;
    int t = threadIdx.x;
    int quad = t >> 6;
    int col  = t & 63;

    __shared__ int    segbase[SUBS];
    __shared__ int    segcnt[SUBS];
    __shared__ int    scnt;
    __shared__ int    cidx[CAP];
    __shared__ float4 sacc[256];
    __shared__ float  wsum[8];
    __shared__ float  sinv;

    if (t < SUBS) {
        int cj = g_cursor[c * SUBS + t];
        g_cursor[c * SUBS + t] = 0;        // restore for next graph replay
        segcnt[t] = cj;
        int x = cj;
        #pragma unroll
        for (int o = 1; o < 32; o <<= 1) {
            int u = __shfl_up_sync(0xffffffffu, x, o);
            if (t >= o) x += u;
        }
        segbase[t] = x - cj;
        if (t == 31) scnt = x;
    }
    __syncthreads();
    int cnt = scnt;

    // compact: 1024 slot positions scanned by 256 threads in 4 passes
    #pragma unroll
    for (int e = t; e < SUBS * SUBCAP; e += 256) {
        int j = e >> 5;            // sub-slot
        int k = e & (SUBCAP - 1);
        if (k < segcnt[j]) cidx[segbase[j] + k] = g_idx[c * CAP + j * SUBCAP + k];
    }
    __syncthreads();

    const float4* f4 = (const float4*)f;
    float4 acc = make_float4(0.f, 0.f, 0.f, 0.f);
    int r = quad;
    for (; r + 12 < cnt; r += 16) {
        float4 v0 = f4[(long)cidx[r     ] * 64 + col];
        float4 v1 = f4[(long)cidx[r +  4] * 64 + col];
        float4 v2 = f4[(long)cidx[r +  8] * 64 + col];
        float4 v3 = f4[(long)cidx[r + 12] * 64 + col];
        acc.x += v0.x + v1.x + v2.x + v3.x;
        acc.y += v0.y + v1.y + v2.y + v3.y;
        acc.z += v0.z + v1.z + v2.z + v3.z;
        acc.w += v0.w + v1.w + v2.w + v3.w;
    }
    for (; r < cnt; r += 4) {
        float4 v = f4[(long)cidx[r] * 64 + col];
        acc.x += v.x; acc.y += v.y; acc.z += v.z; acc.w += v.w;
    }

    sacc[t] = acc;
    __syncthreads();

    float4 mean = make_float4(0.f, 0.f, 0.f, 0.f);
    float ss = 0.f;
    if (t < 64) {
        float4 a = sacc[t], b = sacc[t + 64], c2 = sacc[t + 128], d = sacc[t + 192];
        float inv = 1.0f / (float)((cnt > 0) ? cnt : 1);
        mean.x = (a.x + b.x + c2.x + d.x) * inv;
        mean.y = (a.y + b.y + c2.y + d.y) * inv;
        mean.z = (a.z + b.z + c2.z + d.z) * inv;
        mean.w = (a.w + b.w + c2.w + d.w) * inv;
        ss = mean.x * mean.x + mean.y * mean.y + mean.z * mean.z + mean.w * mean.w;
    }
    #pragma unroll
    for (int o = 16; o > 0; o >>= 1) ss += __shfl_xor_sync(0xffffffffu, ss, o);
    if ((t & 31) == 0) wsum[t >> 5] = ss;
    __syncthreads();
    if (t == 0) {
        float tot = 0.f;
        #pragma unroll
        for (int w = 0; w < 8; w++) tot += wsum[w];
        sinv = (tot > 0.f) ? rsqrtf(tot) : 0.f;
    }
    __syncthreads();
    if (t < 64) {
        float s = sinv;
        float v[4] = {mean.x * s, mean.y * s, mean.z * s, mean.w * s};
        unsigned h[4], l[4];
        #pragma unroll
        for (int i = 0; i < 4; i++) {
            __nv_bfloat16 hb = __float2bfloat16(v[i]);
            float res = v[i] - __bfloat162float(hb);
            __nv_bfloat16 lb = __float2bfloat16(res);
            h[i] = __bfloat16_as_ushort(hb);
            l[i] = __bfloat16_as_ushort(lb);
        }
        g_hi[c * 128 + 2 * t    ] = h[0] | (h[1] << 16);
        g_hi[c * 128 + 2 * t + 1] = h[2] | (h[3] << 16);
        g_lo[c * 128 + 2 * t    ] = l[0] | (l[1] << 16);
        g_lo[c * 128 + 2 * t + 1] = l[2] | (l[3] << 16);
    }
}

// Tensor-core gram-max (R11-proven): 64x64 tiles, 136 upper-tri CTAs,
// ldmatrix fragment loads, split-bf16 3-term mma. Fused loss epilogue.
__global__ void __launch_bounds__(256, 1) grammax_k(float* out, int n_out) {
    extern __shared__ unsigned smw[];
    unsigned* sAh = smw;
    unsigned* sAl = smw + 64 * SROW;
    unsigned* sBh = smw + 2 * 64 * SROW;
    unsigned* sBl = smw + 3 * 64 * SROW;

    int b = blockIdx.x;
    int ti = 0, rl = TILES;
    while (b >= rl) { b -= rl; ti++; rl--; }
    int tj = ti + b;

    int t = threadIdx.x;

    #pragma unroll
    for (int p = 0; p < 32; p++) {
        int idx = p * 256 + t;
        int r = idx >> 7;
        int cw = idx & 127;
        int rA = ti * 64 + r;
        int rB = tj * 64 + r;
        unsigned ah = (rA < NUM_C) ? g_hi[rA * 128 + cw] : 0u;
        unsigned al = (rA < NUM_C) ? g_lo[rA * 128 + cw] : 0u;
        unsigned bh = (rB < NUM_C) ? g_hi[rB * 128 + cw] : 0u;
        unsigned bl = (rB < NUM_C) ? g_lo[rB * 128 + cw] : 0u;
        sAh[r * SROW + cw] = ah;
        sAl[r * SROW + cw] = al;
        sBh[r * SROW + cw] = bh;
        sBl[r * SROW + cw] = bl;
    }
    __syncthreads();

    int w    = t >> 5;
    int lane = t & 31;
    int wrow = (w & 3) * 16;
    int wcol = (w >> 2) * 32;
    int lr   = lane >> 2;
    int lk   = lane & 3;

    int lr8 = lane & 7, grp = lane >> 3;
    int aRow = wrow + lr8 + ((grp & 1) << 3);
    int aK   = (grp >> 1) << 2;
    int bRow0 = wcol + lr8 + ((grp >> 1) << 3);
    int bK   = (grp & 1) << 2;

    unsigned uAhi  = smem_u32(sAh) + 4u * (aRow * SROW + aK);
    unsigned uAlo  = uAhi + 4u * 64 * SROW;
    unsigned uB0hi = smem_u32(sBh) + 4u * (bRow0 * SROW + bK);
    unsigned uB1hi = uB0hi + 4u * 16 * SROW;
    unsigned uB0lo = uB0hi + 4u * 64 * SROW;
    unsigned uB1lo = uB1hi + 4u * 64 * SROW;

    float acc[4][4];
    #pragma unroll
    for (int tn = 0; tn < 4; tn++)
        #pragma unroll
        for (int i = 0; i < 4; i++) acc[tn][i] = 0.f;

    #pragma unroll
    for (int kk = 0; kk < 16; kk++) {
        unsigned ah0,ah1,ah2,ah3, al0,al1,al2,al3;
        ldsm_x4(ah0, ah1, ah2, ah3, uAhi);
        ldsm_x4(al0, al1, al2, al3, uAlo);
        unsigned b00h,b01h,b10h,b11h, b20h,b21h,b30h,b31h;
        ldsm_x4(b00h, b01h, b10h, b11h, uB0hi);
        ldsm_x4(b20h, b21h, b30h, b31h, uB1hi);
        unsigned b00l,b01l,b10l,b11l, b20l,b21l,b30l,b31l;
        ldsm_x4(b00l, b01l, b10l, b11l, uB0lo);
        ldsm_x4(b20l, b21l, b30l, b31l, uB1lo);

        mma_bf16(acc[0][0],acc[0][1],acc[0][2],acc[0][3], ah0,ah1,ah2,ah3, b00h,b01h);
        mma_bf16(acc[0][0],acc[0][1],acc[0][2],acc[0][3], ah0,ah1,ah2,ah3, b00l,b01l);
        mma_bf16(acc[0][0],acc[0][1],acc[0][2],acc[0][3], al0,al1,al2,al3, b00h,b01h);

        mma_bf16(acc[1][0],acc[1][1],acc[1][2],acc[1][3], ah0,ah1,ah2,ah3, b10h,b11h);
        mma_bf16(acc[1][0],acc[1][1],acc[1][2],acc[1][3], ah0,ah1,ah2,ah3, b10l,b11l);
        mma_bf16(acc[1][0],acc[1][1],acc[1][2],acc[1][3], al0,al1,al2,al3, b10h,b11h);

        mma_bf16(acc[2][0],acc[2][1],acc[2][2],acc[2][3], ah0,ah1,ah2,ah3, b20h,b21h);
        mma_bf16(acc[2][0],acc[2][1],acc[2][2],acc[2][3], ah0,ah1,ah2,ah3, b20l,b21l);
        mma_bf16(acc[2][0],acc[2][1],acc[2][2],acc[2][3], al0,al1,al2,al3, b20h,b21h);

        mma_bf16(acc[3][0],acc[3][1],acc[3][2],acc[3][3], ah0,ah1,ah2,ah3, b30h,b31h);
        mma_bf16(acc[3][0],acc[3][1],acc[3][2],acc[3][3], ah0,ah1,ah2,ah3, b30l,b31l);
        mma_bf16(acc[3][0],acc[3][1],acc[3][2],acc[3][3], al0,al1,al2,al3, b30h,b31h);

        uAhi += 32; uAlo += 32;
        uB0hi += 32; uB1hi += 32; uB0lo += 32; uB1lo += 32;
    }

    float lm = -4.0f;
    int gi0 = ti * 64 + wrow + lr;
    #pragma unroll
    for (int tn = 0; tn < 4; tn++) {
        int gj0 = tj * 64 + wcol + tn * 8 + 2 * lk;
        if (gi0     < gj0     && gj0     < NUM_C) lm = fmaxf(lm, acc[tn][0]);
        if (gi0     < gj0 + 1 && gj0 + 1 < NUM_C) lm = fmaxf(lm, acc[tn][1]);
        if (gi0 + 8 < gj0     && gj0     < NUM_C) lm = fmaxf(lm, acc[tn][2]);
        if (gi0 + 8 < gj0 + 1 && gj0 + 1 < NUM_C) lm = fmaxf(lm, acc[tn][3]);
    }
    #pragma unroll
    for (int o = 16; o > 0; o >>= 1) lm = fmaxf(lm, __shfl_xor_sync(0xffffffffu, lm, o));
    __shared__ float wm[8];
    if (lane == 0) wm[w] = lm;
    __syncthreads();
    if (t == 0) {
        float m = wm[0];
        #pragma unroll
        for (int q = 1; q < 8; q++) m = fmaxf(m, wm[q]);
        atomicMax(&g_maxkey, __float_as_int(m + 4.0f));
        __threadfence();
        int ticket = atomicAdd(&g_done, 1);
        if (ticket == gridDim.x - 1) {
            float maxd = __int_as_float(*(volatile int*)&g_maxkey) - 4.0f;
            maxd = fminf(fmaxf(maxd, -1.f), 1.f);
            float mind = 1.0f - maxd;
            float loss = logf(1.0f / (mind + 1e-6f) + 1.0f);
            for (int i = 0; i < n_out; i++) out[i] = loss;
            g_maxkey = 0;    // restore for next graph replay
            g_done = 0;
        }
    }
}

// ---------------------------------------------------------------------------
extern "C" void kernel_launch(void* const* d_in, const int* in_sizes, int n_in,
                              void* d_out, int out_size) {
    const float* features = (const float*)d_in[0];
    const int*   labels   = (const int*)d_in[1];
    int n = in_sizes[1];

    const int smem_gram = 4 * 64 * SROW * (int)sizeof(unsigned); // 135168 B
    cudaFuncSetAttribute(grammax_k, cudaFuncAttributeMaxDynamicSharedMemorySize, smem_gram);

    scatter_k<<<(n + 255) / 256, 256>>>(labels, n);
    gather_k<<<NUM_C, 256>>>(features);
    grammax_k<<<TILES * (TILES + 1) / 2, 256, smem_gram>>>((float*)d_out, out_size);
}